// round 11
// baseline (speedup 1.0000x reference)
#include <cuda_runtime.h>
#include <cuda_bf16.h>
#include <math.h>
#include <stdint.h>

#define S_LEN 8192
#define DIM   1024
#define NH    16
#define HD    64
#define WIN   512
#define KC    3072            // concatenated K = 3 * DIM

// ---------------------------------------------------------------------------
// Scratch
// ---------------------------------------------------------------------------
__device__ float g_qkv[S_LEN * 3 * DIM];
__device__ __nv_bfloat16 g_xc[S_LEN * KC];          // [Xh | Xh | Xl]
__device__ __nv_bfloat16 g_oc[S_LEN * KC];          // [Oh | Oh | Ol]
__device__ __nv_bfloat16 g_wc[4 * DIM * KC];        // per W: [Wh | Wl | Wh]
__device__ __nv_bfloat16 g_qc[S_LEN * KC];          // [qh|qh|ql] per head (rope'd)
__device__ __nv_bfloat16 g_kc[S_LEN * KC];          // [kh|kl|kh] per head (rope'd)
__device__ __nv_bfloat16 g_vt[NH * 2 * HD * S_LEN]; // [h][dcat(128)][s]
__device__ float2 g_cs[S_LEN * 32];                 // (cos,sin) per (s, pair)

// ---------------------------------------------------------------------------
// helpers
// ---------------------------------------------------------------------------
static __device__ __forceinline__ uint32_t smem_u32(const void* p) {
    return (uint32_t)__cvta_generic_to_shared(p);
}
static __device__ __forceinline__ void cp16(uint32_t dst, const void* src) {
    asm volatile("cp.async.cg.shared.global [%0], [%1], 16;" :: "r"(dst), "l"(src));
}
static __device__ __forceinline__ void ldsm4(uint32_t* r, uint32_t addr) {
    asm volatile("ldmatrix.sync.aligned.m8n8.x4.shared.b16 {%0,%1,%2,%3}, [%4];"
                 : "=r"(r[0]), "=r"(r[1]), "=r"(r[2]), "=r"(r[3]) : "r"(addr));
}
static __device__ __forceinline__ void mma16816(float* c, const uint32_t* a,
                                                uint32_t b0, uint32_t b1) {
    asm volatile(
        "mma.sync.aligned.m16n8k16.row.col.f32.bf16.bf16.f32 "
        "{%0,%1,%2,%3}, {%4,%5,%6,%7}, {%8,%9}, {%0,%1,%2,%3};"
        : "+f"(c[0]), "+f"(c[1]), "+f"(c[2]), "+f"(c[3])
        : "r"(a[0]), "r"(a[1]), "r"(a[2]), "r"(a[3]), "r"(b0), "r"(b1));
}
static __device__ __forceinline__ void split2(float a, float b,
                                              uint32_t& hi, uint32_t& lo) {
    __nv_bfloat16 ha = __float2bfloat16(a), hb = __float2bfloat16(b);
    __nv_bfloat162 h(ha, hb);
    hi = *(uint32_t*)&h;
    __nv_bfloat162 l(__float2bfloat16(a - __bfloat162float(ha)),
                     __float2bfloat16(b - __bfloat162float(hb)));
    lo = *(uint32_t*)&l;
}

// ---------------------------------------------------------------------------
// sincos table
// ---------------------------------------------------------------------------
__global__ void sincos_kernel(float2* __restrict__ cs)
{
    int idx = blockIdx.x * blockDim.x + threadIdx.x;
    if (idx >= S_LEN * 32) return;
    int s = idx >> 5, i = idx & 31;
    float e = (float)(2 * i) * (1.0f / 64.0f);
    float inv = 1.0f / powf(10000.0f, e);
    float ang = (float)s * inv;
    float sn, c;
    sincosf(ang, &sn, &c);
    cs[idx] = make_float2(c, sn);
}

// ---------------------------------------------------------------------------
// fp32 -> bf16 3-segment splits
// ---------------------------------------------------------------------------
__global__ void split3_kernel(const float* __restrict__ src,
                              __nv_bfloat16* __restrict__ dst, int nelem)
{
    int i = (blockIdx.x * blockDim.x + threadIdx.x) * 4;
    if (i >= nelem) return;
    int r = i >> 10;
    int c = i & 1023;
    float4 v = *(const float4*)(src + i);
    float f[4] = {v.x, v.y, v.z, v.w};
    __nv_bfloat16 h[4], l[4];
#pragma unroll
    for (int j = 0; j < 4; j++) {
        h[j] = __float2bfloat16(f[j]);
        l[j] = __float2bfloat16(f[j] - __bfloat162float(h[j]));
    }
    __nv_bfloat16* row = dst + (size_t)r * KC + c;
    *(__nv_bfloat162*)(row)        = __nv_bfloat162(h[0], h[1]);
    *(__nv_bfloat162*)(row + 2)    = __nv_bfloat162(h[2], h[3]);
    *(__nv_bfloat162*)(row + 1024) = __nv_bfloat162(h[0], h[1]);
    *(__nv_bfloat162*)(row + 1026) = __nv_bfloat162(h[2], h[3]);
    *(__nv_bfloat162*)(row + 2048) = __nv_bfloat162(l[0], l[1]);
    *(__nv_bfloat162*)(row + 2050) = __nv_bfloat162(l[2], l[3]);
}

__global__ void split3_w_kernel(const float* __restrict__ W0,
                                const float* __restrict__ W1,
                                const float* __restrict__ W2,
                                const float* __restrict__ W3,
                                __nv_bfloat16* __restrict__ dstbase)
{
    const float* srcs[4] = {W0, W1, W2, W3};
    const float* src = srcs[blockIdx.y];
    __nv_bfloat16* dst = dstbase + (size_t)blockIdx.y * DIM * KC;

    int i = (blockIdx.x * blockDim.x + threadIdx.x) * 4;
    if (i >= DIM * DIM) return;
    int r = i >> 10;
    int c = i & 1023;
    float4 v = *(const float4*)(src + i);
    float f[4] = {v.x, v.y, v.z, v.w};
    __nv_bfloat16 h[4], l[4];
#pragma unroll
    for (int j = 0; j < 4; j++) {
        h[j] = __float2bfloat16(f[j]);
        l[j] = __float2bfloat16(f[j] - __bfloat162float(h[j]));
    }
    __nv_bfloat16* row = dst + (size_t)r * KC + c;
    *(__nv_bfloat162*)(row)        = __nv_bfloat162(h[0], h[1]);
    *(__nv_bfloat162*)(row + 2)    = __nv_bfloat162(h[2], h[3]);
    *(__nv_bfloat162*)(row + 1024) = __nv_bfloat162(l[0], l[1]);
    *(__nv_bfloat162*)(row + 1026) = __nv_bfloat162(l[2], l[3]);
    *(__nv_bfloat162*)(row + 2048) = __nv_bfloat162(h[0], h[1]);
    *(__nv_bfloat162*)(row + 2050) = __nv_bfloat162(h[2], h[3]);
}

// ---------------------------------------------------------------------------
// bf16 mma GEMM: BK=64, 2-stage cp.async, hoisted LDSM addresses,
// unroll-2 mainloop (constant-folds stage select).
// ---------------------------------------------------------------------------
#define BM 128
#define BK 64
#define NKB2 (KC / BK)       // 48
#define LDS_ROW 72           // 64 + 8 pad (144B row)
#define A_STG (BM * LDS_ROW)

template <int BNT>
__global__ __launch_bounds__(128, (BNT == 64 ? 4 : 3)) void gemm_mma(
    const __nv_bfloat16* __restrict__ A,
    const __nv_bfloat16* __restrict__ B,
    float* __restrict__ C, int Nld)
{
    constexpr int B_STG = BNT * LDS_ROW;
    constexpr int WN = BNT / 2;
    constexpr int NI = WN / 8;

    extern __shared__ __nv_bfloat16 gsm[];
    __nv_bfloat16* AsB = gsm;
    __nv_bfloat16* BsB = gsm + 2 * A_STG;

    const int tid = threadIdx.x;
    const int lane = tid & 31;
    const int wid = tid >> 5;
    const int wm = (wid & 1) * 64;
    const int wn = (wid >> 1) * WN;
    const int m0 = blockIdx.x * BM;
    const int n0 = blockIdx.y * BNT;

    const int r0 = tid >> 3, g0 = (tid & 7) * 8;

    auto load_stage = [&](int kb, int slot) {
        __nv_bfloat16* As = AsB + slot * A_STG;
        __nv_bfloat16* Bs = BsB + slot * B_STG;
#pragma unroll
        for (int j = 0; j < 8; j++) {
            int row = r0 + j * 16;
            cp16(smem_u32(&As[row * LDS_ROW + g0]),
                 A + (size_t)(m0 + row) * KC + kb * BK + g0);
        }
#pragma unroll
        for (int j = 0; j < BNT / 16; j++) {
            int row = r0 + j * 16;
            cp16(smem_u32(&Bs[row * LDS_ROW + g0]),
                 B + (size_t)(n0 + row) * KC + kb * BK + g0);
        }
        asm volatile("cp.async.commit_group;");
    };

    float acc[4][NI][4];
#pragma unroll
    for (int mi = 0; mi < 4; mi++)
#pragma unroll
        for (int ni = 0; ni < NI; ni++)
#pragma unroll
            for (int q = 0; q < 4; q++) acc[mi][ni][q] = 0.f;

    load_stage(0, 0);

    const int lrow = lane & 15;
    const int lcol = (lane >> 4) * 8;

    // hoisted LDSM base addresses (stage 0, ks 0)
    uint32_t aAddr[4], bAddr[NI / 2];
#pragma unroll
    for (int mi = 0; mi < 4; mi++)
        aAddr[mi] = smem_u32(&AsB[(wm + mi * 16 + lrow) * LDS_ROW + lcol]);
#pragma unroll
    for (int g = 0; g < NI / 2; g++)
        bAddr[g] = smem_u32(&BsB[(wn + g * 16 + lrow) * LDS_ROW + lcol]);

#pragma unroll 2
    for (int kb = 0; kb < NKB2; kb++) {
        asm volatile("cp.async.wait_group 0;");
        __syncthreads();
        if (kb + 1 < NKB2) load_stage(kb + 1, (kb + 1) & 1);

        const uint32_t sA = (uint32_t)((kb & 1) * (A_STG * 2));
        const uint32_t sB = (uint32_t)((kb & 1) * (B_STG * 2));

#pragma unroll
        for (int ks = 0; ks < 4; ks++) {
            const uint32_t ko = ks * 32;   // 16 bf16 = 32 bytes
            uint32_t af[4][4], bfr[NI / 2][4];
#pragma unroll
            for (int mi = 0; mi < 4; mi++)
                ldsm4(af[mi], aAddr[mi] + sA + ko);
#pragma unroll
            for (int g = 0; g < NI / 2; g++)
                ldsm4(bfr[g], bAddr[g] + sB + ko);
#pragma unroll
            for (int g = 0; g < NI / 2; g++)
#pragma unroll
                for (int mi = 0; mi < 4; mi++) {
                    mma16816(acc[mi][g * 2 + 0], af[mi], bfr[g][0], bfr[g][2]);
                    mma16816(acc[mi][g * 2 + 1], af[mi], bfr[g][1], bfr[g][3]);
                }
        }
    }

    const int erow = lane >> 2;
    const int ecol = (lane & 3) * 2;
#pragma unroll
    for (int mi = 0; mi < 4; mi++)
#pragma unroll
        for (int ni = 0; ni < NI; ni++) {
            int row = m0 + wm + mi * 16 + erow;
            int col = n0 + wn + ni * 8 + ecol;
            *(float2*)(C + (size_t)row * Nld + col) =
                make_float2(acc[mi][ni][0], acc[mi][ni][1]);
            *(float2*)(C + (size_t)(row + 8) * Nld + col) =
                make_float2(acc[mi][ni][2], acc[mi][ni][3]);
        }
}

#define GEMM_SMEM_128 (2 * (A_STG + 128 * LDS_ROW) * 2)   // 73728
#define GEMM_SMEM_64  (2 * (A_STG + 64 * LDS_ROW) * 2)    // 55296

// ---------------------------------------------------------------------------
// rope_split with sincos table
// ---------------------------------------------------------------------------
__global__ __launch_bounds__(256) void rope_split_kernel(
    const float* __restrict__ qkv, const float2* __restrict__ cstab,
    __nv_bfloat16* __restrict__ qc, __nv_bfloat16* __restrict__ kc,
    __nv_bfloat16* __restrict__ vt)
{
    __shared__ float vsm[64][68];

    const int tid = threadIdx.x;
    const int sb = blockIdx.x * 64;
    const int h = blockIdx.y;
    const int r = tid >> 2;
    const int pg = tid & 3;

    {
        int s = sb + r;
        const float* qrow = qkv + (size_t)s * (3 * DIM) + h * HD;
        const float* krow = qrow + DIM;
#pragma unroll
        for (int u = 0; u < 4; u++) {
            int c = pg * 16 + u * 4;
            float4 qv = *(const float4*)(qrow + c);
            float4 kv = *(const float4*)(krow + c);
            float outq[4], outk[4];
#pragma unroll
            for (int pp = 0; pp < 2; pp++) {
                int ip = (c >> 1) + pp;
                float2 cspair = cstab[(s << 5) + ip];
                float cs = cspair.x, sn = cspair.y;
                float qx = pp ? qv.z : qv.x, qy = pp ? qv.w : qv.y;
                float kx = pp ? kv.z : kv.x, ky = pp ? kv.w : kv.y;
                outq[2 * pp + 0] = qx * cs - qy * sn;
                outq[2 * pp + 1] = qx * sn + qy * cs;
                outk[2 * pp + 0] = kx * cs - ky * sn;
                outk[2 * pp + 1] = kx * sn + ky * cs;
            }
            uint32_t qh0, ql0, qh1, ql1, kh0, kl0, kh1, kl1;
            split2(outq[0], outq[1], qh0, ql0);
            split2(outq[2], outq[3], qh1, ql1);
            split2(outk[0], outk[1], kh0, kl0);
            split2(outk[2], outk[3], kh1, kl1);
            __nv_bfloat16* qd = qc + (size_t)s * KC + h * 192 + c;
            __nv_bfloat16* kd = kc + (size_t)s * KC + h * 192 + c;
            *(uint32_t*)(qd)       = qh0; *(uint32_t*)(qd + 2)   = qh1;
            *(uint32_t*)(qd + 64)  = qh0; *(uint32_t*)(qd + 66)  = qh1;
            *(uint32_t*)(qd + 128) = ql0; *(uint32_t*)(qd + 130) = ql1;
            *(uint32_t*)(kd)       = kh0; *(uint32_t*)(kd + 2)   = kh1;
            *(uint32_t*)(kd + 64)  = kl0; *(uint32_t*)(kd + 66)  = kl1;
            *(uint32_t*)(kd + 128) = kh0; *(uint32_t*)(kd + 130) = kh1;
        }
    }

    {
        const float* vrow = qkv + (size_t)(sb + r) * (3 * DIM) + 2 * DIM + h * HD;
#pragma unroll
        for (int u = 0; u < 4; u++) {
            int c = pg * 16 + u * 4;
            *(float4*)&vsm[r][c] = *(const float4*)(vrow + c);
        }
    }
    __syncthreads();
    {
        int dcat = tid & 127;
        int sh = (tid >> 7) * 32;
        int d = dcat & 63;
        bool lo = dcat >= 64;
        uint32_t packs[16];
#pragma unroll
        for (int j = 0; j < 16; j++) {
            float f0 = vsm[sh + 2 * j][d];
            float f1 = vsm[sh + 2 * j + 1][d];
            uint32_t hi, lw;
            split2(f0, f1, hi, lw);
            packs[j] = lo ? lw : hi;
        }
        __nv_bfloat16* dst = vt + ((size_t)(h * 128 + dcat)) * S_LEN + sb + sh;
#pragma unroll
        for (int j = 0; j < 4; j++)
            *(uint4*)(dst + j * 8) = make_uint4(packs[4 * j], packs[4 * j + 1],
                                                packs[4 * j + 2], packs[4 * j + 3]);
    }
}

// ---------------------------------------------------------------------------
// Tensor-core sliding-window flash attention: BQ=64, 128 threads,
// single-buffered (3 CTAs/SM), interior tiles skip masking entirely.
// Only the diagonal tile (kbase==qbase) and oldest tile (kbase==qbase-512)
// have any invalid (query,key) pairs.
// ---------------------------------------------------------------------------
#define QLD 200      // 192 + 8 pad
#define VLD 72       // 64 + 8 pad
#define SWA_SMEM (64 * QLD * 2 + 64 * QLD * 2 + 128 * VLD * 2)  // 69632

__global__ __launch_bounds__(128) void swa_mma_kernel(
    const __nv_bfloat16* __restrict__ qc, const __nv_bfloat16* __restrict__ kc,
    const __nv_bfloat16* __restrict__ vt, __nv_bfloat16* __restrict__ oc)
{
    extern __shared__ char smem[];
    __nv_bfloat16* Qs = (__nv_bfloat16*)smem;                      // [64][QLD]
    __nv_bfloat16* Ks = (__nv_bfloat16*)(smem + 64 * QLD * 2);     // [64][QLD]
    __nv_bfloat16* Vc = (__nv_bfloat16*)(smem + 2 * 64 * QLD * 2); // [128][VLD]

    const int tid = threadIdx.x;
    const int lane = tid & 31;
    const int w = tid >> 5;
    const int qbase = blockIdx.x * 64;
    const int h = blockIdx.y;
    const int lrow = lane & 15;
    const int lcol = (lane >> 4) * 8;

    {
#pragma unroll
        for (int i = 0; i < 12; i++) {
            int c = tid + i * 128;
            int row = c / 24, off = (c % 24) * 8;
            cp16(smem_u32(&Qs[row * QLD + off]),
                 qc + (size_t)(qbase + row) * KC + h * 192 + off);
        }
        asm volatile("cp.async.commit_group;");
    }

    float oacc[8][4];
#pragma unroll
    for (int b = 0; b < 8; b++)
#pragma unroll
        for (int q = 0; q < 4; q++) oacc[b][q] = 0.f;
    float mrun0 = -1e30f, mrun1 = -1e30f, lrun0 = 0.f, lrun1 = 0.f;

    const int qg0 = qbase + w * 16 + (lane >> 2);
    const int qg1 = qg0 + 8;

    for (int t = 0; t < 9; t++) {
        int kbase = qbase - 512 + t * 64;
        if (kbase < 0) continue;
        __syncthreads();

#pragma unroll
        for (int i = 0; i < 12; i++) {
            int c = tid + i * 128;
            int row = c / 24, off = (c % 24) * 8;
            cp16(smem_u32(&Ks[row * QLD + off]),
                 kc + (size_t)(kbase + row) * KC + h * 192 + off);
        }
#pragma unroll
        for (int i = 0; i < 8; i++) {
            int c = tid + i * 128;
            int dcat = c >> 3, j0 = (c & 7) * 8;
            cp16(smem_u32(&Vc[dcat * VLD + j0]),
                 vt + ((size_t)(h * 128 + dcat)) * S_LEN + kbase + j0);
        }
        asm volatile("cp.async.commit_group;");
        asm volatile("cp.async.wait_group 0;");
        __syncthreads();

        float sacc[8][4];
#pragma unroll
        for (int b = 0; b < 8; b++)
#pragma unroll
            for (int q = 0; q < 4; q++) sacc[b][q] = 0.f;
#pragma unroll
        for (int ks = 0; ks < 12; ks++) {
            uint32_t af[4];
            ldsm4(af, smem_u32(&Qs[(w * 16 + lrow) * QLD + ks * 16 + lcol]));
#pragma unroll
            for (int g = 0; g < 4; g++) {
                uint32_t bf[4];
                ldsm4(bf, smem_u32(&Ks[(g * 16 + lrow) * QLD + ks * 16 + lcol]));
                mma16816(sacc[g * 2 + 0], af, bf[0], bf[2]);
                mma16816(sacc[g * 2 + 1], af, bf[1], bf[3]);
            }
        }

        // Only diagonal / oldest tiles contain invalid pairs.
        const bool edge = (kbase == qbase) || (kbase == qbase - 512);
        if (edge) {
#pragma unroll
            for (int b = 0; b < 8; b++) {
                int j0 = kbase + b * 8 + (lane & 3) * 2;
#pragma unroll
                for (int q = 0; q < 4; q++) {
                    int kg = j0 + (q & 1);
                    int qg = (q < 2) ? qg0 : qg1;
                    bool valid = (kg <= qg) && (kg + (WIN - 1) >= qg);
                    sacc[b][q] = valid ? sacc[b][q] * 0.125f : -1e30f;
                }
            }
        } else {
#pragma unroll
            for (int b = 0; b < 8; b++)
#pragma unroll
                for (int q = 0; q < 4; q++) sacc[b][q] *= 0.125f;
        }

        float rm0 = -1e30f, rm1 = -1e30f;
#pragma unroll
        for (int b = 0; b < 8; b++) {
            rm0 = fmaxf(rm0, fmaxf(sacc[b][0], sacc[b][1]));
            rm1 = fmaxf(rm1, fmaxf(sacc[b][2], sacc[b][3]));
        }
        rm0 = fmaxf(rm0, __shfl_xor_sync(0xffffffffu, rm0, 1));
        rm0 = fmaxf(rm0, __shfl_xor_sync(0xffffffffu, rm0, 2));
        rm1 = fmaxf(rm1, __shfl_xor_sync(0xffffffffu, rm1, 1));
        rm1 = fmaxf(rm1, __shfl_xor_sync(0xffffffffu, rm1, 2));

        float mn0 = fmaxf(mrun0, rm0), mn1 = fmaxf(mrun1, rm1);
        float sc0 = __expf(mrun0 - mn0), sc1 = __expf(mrun1 - mn1);
        float rs0 = 0.f, rs1 = 0.f;
        if (edge) {
#pragma unroll
            for (int b = 0; b < 8; b++) {
                float p0 = (sacc[b][0] > -5e29f) ? __expf(sacc[b][0] - mn0) : 0.f;
                float p1 = (sacc[b][1] > -5e29f) ? __expf(sacc[b][1] - mn0) : 0.f;
                float p2 = (sacc[b][2] > -5e29f) ? __expf(sacc[b][2] - mn1) : 0.f;
                float p3 = (sacc[b][3] > -5e29f) ? __expf(sacc[b][3] - mn1) : 0.f;
                sacc[b][0] = p0; sacc[b][1] = p1; sacc[b][2] = p2; sacc[b][3] = p3;
                rs0 += p0 + p1;
                rs1 += p2 + p3;
            }
        } else {
#pragma unroll
            for (int b = 0; b < 8; b++) {
                float p0 = __expf(sacc[b][0] - mn0);
                float p1 = __expf(sacc[b][1] - mn0);
                float p2 = __expf(sacc[b][2] - mn1);
                float p3 = __expf(sacc[b][3] - mn1);
                sacc[b][0] = p0; sacc[b][1] = p1; sacc[b][2] = p2; sacc[b][3] = p3;
                rs0 += p0 + p1;
                rs1 += p2 + p3;
            }
        }
        rs0 += __shfl_xor_sync(0xffffffffu, rs0, 1);
        rs0 += __shfl_xor_sync(0xffffffffu, rs0, 2);
        rs1 += __shfl_xor_sync(0xffffffffu, rs1, 1);
        rs1 += __shfl_xor_sync(0xffffffffu, rs1, 2);
        lrun0 = lrun0 * sc0 + rs0;
        lrun1 = lrun1 * sc1 + rs1;
        mrun0 = mn0;
        mrun1 = mn1;
#pragma unroll
        for (int b = 0; b < 8; b++) {
            oacc[b][0] *= sc0; oacc[b][1] *= sc0;
            oacc[b][2] *= sc1; oacc[b][3] *= sc1;
        }

#pragma unroll
        for (int ks = 0; ks < 4; ks++) {
            uint32_t aH[4], aL[4];
            split2(sacc[2 * ks][0],     sacc[2 * ks][1],     aH[0], aL[0]);
            split2(sacc[2 * ks][2],     sacc[2 * ks][3],     aH[1], aL[1]);
            split2(sacc[2 * ks + 1][0], sacc[2 * ks + 1][1], aH[2], aL[2]);
            split2(sacc[2 * ks + 1][2], sacc[2 * ks + 1][3], aH[3], aL[3]);
#pragma unroll
            for (int db = 0; db < 4; db++) {
                uint32_t bh[4], bl[4];
                ldsm4(bh, smem_u32(&Vc[(db * 16 + lrow) * VLD + ks * 16 + lcol]));
                ldsm4(bl, smem_u32(&Vc[((64 + db * 16) + lrow) * VLD + ks * 16 + lcol]));
                mma16816(oacc[2 * db + 0], aH, bh[0], bh[2]);
                mma16816(oacc[2 * db + 1], aH, bh[1], bh[3]);
                mma16816(oacc[2 * db + 0], aL, bh[0], bh[2]);
                mma16816(oacc[2 * db + 1], aL, bh[1], bh[3]);
                mma16816(oacc[2 * db + 0], aH, bl[0], bl[2]);
                mma16816(oacc[2 * db + 1], aH, bl[1], bl[3]);
            }
        }
    }

    float inv0 = 1.0f / lrun0, inv1 = 1.0f / lrun1;
#pragma unroll
    for (int b = 0; b < 8; b++) {
        int d = b * 8 + (lane & 3) * 2;
        uint32_t hi0, lo0, hi1, lo1;
        split2(oacc[b][0] * inv0, oacc[b][1] * inv0, hi0, lo0);
        split2(oacc[b][2] * inv1, oacc[b][3] * inv1, hi1, lo1);
        __nv_bfloat16* d0 = oc + (size_t)qg0 * KC + h * HD + d;
        __nv_bfloat16* d1 = oc + (size_t)qg1 * KC + h * HD + d;
        *(uint32_t*)(d0)        = hi0;
        *(uint32_t*)(d0 + 1024) = hi0;
        *(uint32_t*)(d0 + 2048) = lo0;
        *(uint32_t*)(d1)        = hi1;
        *(uint32_t*)(d1 + 1024) = hi1;
        *(uint32_t*)(d1 + 2048) = lo1;
    }
}

// ---------------------------------------------------------------------------
// Launch
// ---------------------------------------------------------------------------
extern "C" void kernel_launch(void* const* d_in, const int* in_sizes, int n_in,
                              void* d_out, int out_size)
{
    (void)in_sizes; (void)n_in; (void)out_size;

    const float* x = (const float*)d_in[0];
    const float* W[4] = {(const float*)d_in[1], (const float*)d_in[2],
                         (const float*)d_in[3], (const float*)d_in[4]};
    float* out = (float*)d_out;

    float* qkv;
    float2* cstab;
    __nv_bfloat16 *xc, *oc, *wc, *qc, *kc, *vt;
    cudaGetSymbolAddress((void**)&qkv, g_qkv);
    cudaGetSymbolAddress((void**)&cstab, g_cs);
    cudaGetSymbolAddress((void**)&xc, g_xc);
    cudaGetSymbolAddress((void**)&oc, g_oc);
    cudaGetSymbolAddress((void**)&wc, g_wc);
    cudaGetSymbolAddress((void**)&qc, g_qc);
    cudaGetSymbolAddress((void**)&kc, g_kc);
    cudaGetSymbolAddress((void**)&vt, g_vt);

    cudaFuncSetAttribute(gemm_mma<128>, cudaFuncAttributeMaxDynamicSharedMemorySize, GEMM_SMEM_128);
    cudaFuncSetAttribute(gemm_mma<64>,  cudaFuncAttributeMaxDynamicSharedMemorySize, GEMM_SMEM_64);
    cudaFuncSetAttribute(swa_mma_kernel, cudaFuncAttributeMaxDynamicSharedMemorySize, SWA_SMEM);

    const int nx = S_LEN * DIM;
    const int nw = DIM * DIM;

    sincos_kernel<<<(S_LEN * 32) / 256, 256>>>(cstab);
    split3_kernel<<<nx / 4 / 256, 256>>>(x, xc, nx);
    split3_w_kernel<<<dim3(nw / 4 / 256, 4), 256>>>(W[0], W[1], W[2], W[3], wc);

    gemm_mma<128><<<dim3(S_LEN / BM, 3 * DIM / 128), 128, GEMM_SMEM_128>>>(
        xc, wc, qkv, 3 * DIM);

    rope_split_kernel<<<dim3(S_LEN / 64, NH), 256>>>(qkv, cstab, qc, kc, vt);

    swa_mma_kernel<<<dim3(S_LEN / 64, NH), 128, SWA_SMEM>>>(qc, kc, vt, oc);

    gemm_mma<64><<<dim3(S_LEN / BM, DIM / 64), 128, GEMM_SMEM_64>>>(
        oc, wc + (size_t)3 * DIM * KC, out, DIM);
}

// round 13
// speedup vs baseline: 1.1039x; 1.1039x over previous
#include <cuda_runtime.h>
#include <cuda_bf16.h>
#include <math.h>
#include <stdint.h>

#define S_LEN 8192
#define DIM   1024
#define NH    16
#define HD    64
#define WIN   512
#define KC    3072            // concatenated K = 3 * DIM

// ---------------------------------------------------------------------------
// Scratch
// ---------------------------------------------------------------------------
__device__ float g_qkv[S_LEN * 3 * DIM];
__device__ __nv_bfloat16 g_xc[S_LEN * KC];          // [Xh | Xh | Xl]
__device__ __nv_bfloat16 g_oc[S_LEN * KC];          // [Oh | Oh | Ol]
__device__ __nv_bfloat16 g_wc[4 * DIM * KC];        // per W: [Wh | Wl | Wh]
__device__ __nv_bfloat16 g_qc[S_LEN * KC];          // [qh|qh|ql] per head (rope'd)
__device__ __nv_bfloat16 g_kc[S_LEN * KC];          // [kh|kl|kh] per head (rope'd)
__device__ __nv_bfloat16 g_vt[NH * 2 * HD * S_LEN]; // [h][dcat(128)][s]
__device__ float2 g_cs[S_LEN * 32];                 // (cos,sin) per (s, pair)

// ---------------------------------------------------------------------------
// helpers
// ---------------------------------------------------------------------------
static __device__ __forceinline__ uint32_t smem_u32(const void* p) {
    return (uint32_t)__cvta_generic_to_shared(p);
}
static __device__ __forceinline__ void cp16(uint32_t dst, const void* src) {
    asm volatile("cp.async.cg.shared.global [%0], [%1], 16;" :: "r"(dst), "l"(src));
}
static __device__ __forceinline__ void ldsm4(uint32_t* r, uint32_t addr) {
    asm volatile("ldmatrix.sync.aligned.m8n8.x4.shared.b16 {%0,%1,%2,%3}, [%4];"
                 : "=r"(r[0]), "=r"(r[1]), "=r"(r[2]), "=r"(r[3]) : "r"(addr));
}
static __device__ __forceinline__ void mma16816(float* c, const uint32_t* a,
                                                uint32_t b0, uint32_t b1) {
    asm volatile(
        "mma.sync.aligned.m16n8k16.row.col.f32.bf16.bf16.f32 "
        "{%0,%1,%2,%3}, {%4,%5,%6,%7}, {%8,%9}, {%0,%1,%2,%3};"
        : "+f"(c[0]), "+f"(c[1]), "+f"(c[2]), "+f"(c[3])
        : "r"(a[0]), "r"(a[1]), "r"(a[2]), "r"(a[3]), "r"(b0), "r"(b1));
}
static __device__ __forceinline__ void split2(float a, float b,
                                              uint32_t& hi, uint32_t& lo) {
    __nv_bfloat16 ha = __float2bfloat16(a), hb = __float2bfloat16(b);
    __nv_bfloat162 h(ha, hb);
    hi = *(uint32_t*)&h;
    __nv_bfloat162 l(__float2bfloat16(a - __bfloat162float(ha)),
                     __float2bfloat16(b - __bfloat162float(hb)));
    lo = *(uint32_t*)&l;
}

// ---------------------------------------------------------------------------
// sincos table
// ---------------------------------------------------------------------------
__global__ void sincos_kernel(float2* __restrict__ cs)
{
    int idx = blockIdx.x * blockDim.x + threadIdx.x;
    if (idx >= S_LEN * 32) return;
    int s = idx >> 5, i = idx & 31;
    float e = (float)(2 * i) * (1.0f / 64.0f);
    float inv = 1.0f / powf(10000.0f, e);
    float ang = (float)s * inv;
    float sn, c;
    sincosf(ang, &sn, &c);
    cs[idx] = make_float2(c, sn);
}

// ---------------------------------------------------------------------------
// fp32 -> bf16 3-segment splits
// ---------------------------------------------------------------------------
__global__ void split3_kernel(const float* __restrict__ src,
                              __nv_bfloat16* __restrict__ dst, int nelem)
{
    int i = (blockIdx.x * blockDim.x + threadIdx.x) * 4;
    if (i >= nelem) return;
    int r = i >> 10;
    int c = i & 1023;
    float4 v = *(const float4*)(src + i);
    float f[4] = {v.x, v.y, v.z, v.w};
    __nv_bfloat16 h[4], l[4];
#pragma unroll
    for (int j = 0; j < 4; j++) {
        h[j] = __float2bfloat16(f[j]);
        l[j] = __float2bfloat16(f[j] - __bfloat162float(h[j]));
    }
    __nv_bfloat16* row = dst + (size_t)r * KC + c;
    *(__nv_bfloat162*)(row)        = __nv_bfloat162(h[0], h[1]);
    *(__nv_bfloat162*)(row + 2)    = __nv_bfloat162(h[2], h[3]);
    *(__nv_bfloat162*)(row + 1024) = __nv_bfloat162(h[0], h[1]);
    *(__nv_bfloat162*)(row + 1026) = __nv_bfloat162(h[2], h[3]);
    *(__nv_bfloat162*)(row + 2048) = __nv_bfloat162(l[0], l[1]);
    *(__nv_bfloat162*)(row + 2050) = __nv_bfloat162(l[2], l[3]);
}

__global__ void split3_w_kernel(const float* __restrict__ W0,
                                const float* __restrict__ W1,
                                const float* __restrict__ W2,
                                const float* __restrict__ W3,
                                __nv_bfloat16* __restrict__ dstbase)
{
    const float* srcs[4] = {W0, W1, W2, W3};
    const float* src = srcs[blockIdx.y];
    __nv_bfloat16* dst = dstbase + (size_t)blockIdx.y * DIM * KC;

    int i = (blockIdx.x * blockDim.x + threadIdx.x) * 4;
    if (i >= DIM * DIM) return;
    int r = i >> 10;
    int c = i & 1023;
    float4 v = *(const float4*)(src + i);
    float f[4] = {v.x, v.y, v.z, v.w};
    __nv_bfloat16 h[4], l[4];
#pragma unroll
    for (int j = 0; j < 4; j++) {
        h[j] = __float2bfloat16(f[j]);
        l[j] = __float2bfloat16(f[j] - __bfloat162float(h[j]));
    }
    __nv_bfloat16* row = dst + (size_t)r * KC + c;
    *(__nv_bfloat162*)(row)        = __nv_bfloat162(h[0], h[1]);
    *(__nv_bfloat162*)(row + 2)    = __nv_bfloat162(h[2], h[3]);
    *(__nv_bfloat162*)(row + 1024) = __nv_bfloat162(l[0], l[1]);
    *(__nv_bfloat162*)(row + 1026) = __nv_bfloat162(l[2], l[3]);
    *(__nv_bfloat162*)(row + 2048) = __nv_bfloat162(h[0], h[1]);
    *(__nv_bfloat162*)(row + 2050) = __nv_bfloat162(h[2], h[3]);
}

// ---------------------------------------------------------------------------
// bf16 mma GEMM: BK=64, 2-stage cp.async, one barrier per iteration.
// (R10 mainloop form — ptxas schedules LDSM addressing best on its own.)
// ---------------------------------------------------------------------------
#define BM 128
#define BK 64
#define NKB2 (KC / BK)       // 48
#define LDS_ROW 72           // 64 + 8 pad (144B row)
#define A_STG (BM * LDS_ROW)

template <int BNT>
__global__ __launch_bounds__(128, (BNT == 64 ? 4 : 3)) void gemm_mma(
    const __nv_bfloat16* __restrict__ A,
    const __nv_bfloat16* __restrict__ B,
    float* __restrict__ C, int Nld)
{
    constexpr int B_STG = BNT * LDS_ROW;
    constexpr int WN = BNT / 2;
    constexpr int NI = WN / 8;

    extern __shared__ __nv_bfloat16 gsm[];
    __nv_bfloat16* AsB = gsm;
    __nv_bfloat16* BsB = gsm + 2 * A_STG;

    const int tid = threadIdx.x;
    const int lane = tid & 31;
    const int wid = tid >> 5;
    const int wm = (wid & 1) * 64;
    const int wn = (wid >> 1) * WN;
    const int m0 = blockIdx.x * BM;
    const int n0 = blockIdx.y * BNT;

    const int r0 = tid >> 3, g0 = (tid & 7) * 8;

    auto load_stage = [&](int kb, int slot) {
        __nv_bfloat16* As = AsB + slot * A_STG;
        __nv_bfloat16* Bs = BsB + slot * B_STG;
#pragma unroll
        for (int j = 0; j < 8; j++) {
            int row = r0 + j * 16;
            cp16(smem_u32(&As[row * LDS_ROW + g0]),
                 A + (size_t)(m0 + row) * KC + kb * BK + g0);
        }
#pragma unroll
        for (int j = 0; j < BNT / 16; j++) {
            int row = r0 + j * 16;
            cp16(smem_u32(&Bs[row * LDS_ROW + g0]),
                 B + (size_t)(n0 + row) * KC + kb * BK + g0);
        }
        asm volatile("cp.async.commit_group;");
    };

    float acc[4][NI][4];
#pragma unroll
    for (int mi = 0; mi < 4; mi++)
#pragma unroll
        for (int ni = 0; ni < NI; ni++)
#pragma unroll
            for (int q = 0; q < 4; q++) acc[mi][ni][q] = 0.f;

    load_stage(0, 0);

    const int lrow = lane & 15;
    const int lcol = (lane >> 4) * 8;

    for (int kb = 0; kb < NKB2; kb++) {
        asm volatile("cp.async.wait_group 0;");
        __syncthreads();
        if (kb + 1 < NKB2) load_stage(kb + 1, (kb + 1) & 1);

        const __nv_bfloat16* As = AsB + (kb & 1) * A_STG;
        const __nv_bfloat16* Bs = BsB + (kb & 1) * B_STG;

#pragma unroll
        for (int ks = 0; ks < 4; ks++) {
            const int koff = ks * 16;
            uint32_t af[4][4], bfr[NI / 2][4];
#pragma unroll
            for (int mi = 0; mi < 4; mi++)
                ldsm4(af[mi], smem_u32(&As[(wm + mi * 16 + lrow) * LDS_ROW + koff + lcol]));
#pragma unroll
            for (int g = 0; g < NI / 2; g++)
                ldsm4(bfr[g], smem_u32(&Bs[(wn + g * 16 + lrow) * LDS_ROW + koff + lcol]));
#pragma unroll
            for (int g = 0; g < NI / 2; g++)
#pragma unroll
                for (int mi = 0; mi < 4; mi++) {
                    mma16816(acc[mi][g * 2 + 0], af[mi], bfr[g][0], bfr[g][2]);
                    mma16816(acc[mi][g * 2 + 1], af[mi], bfr[g][1], bfr[g][3]);
                }
        }
    }

    const int erow = lane >> 2;
    const int ecol = (lane & 3) * 2;
#pragma unroll
    for (int mi = 0; mi < 4; mi++)
#pragma unroll
        for (int ni = 0; ni < NI; ni++) {
            int row = m0 + wm + mi * 16 + erow;
            int col = n0 + wn + ni * 8 + ecol;
            *(float2*)(C + (size_t)row * Nld + col) =
                make_float2(acc[mi][ni][0], acc[mi][ni][1]);
            *(float2*)(C + (size_t)(row + 8) * Nld + col) =
                make_float2(acc[mi][ni][2], acc[mi][ni][3]);
        }
}

#define GEMM_SMEM_128 (2 * (A_STG + 128 * LDS_ROW) * 2)   // 73728
#define GEMM_SMEM_64  (2 * (A_STG + 64 * LDS_ROW) * 2)    // 55296

// ---------------------------------------------------------------------------
// rope_split with sincos table
// ---------------------------------------------------------------------------
__global__ __launch_bounds__(256) void rope_split_kernel(
    const float* __restrict__ qkv, const float2* __restrict__ cstab,
    __nv_bfloat16* __restrict__ qc, __nv_bfloat16* __restrict__ kc,
    __nv_bfloat16* __restrict__ vt)
{
    __shared__ float vsm[64][68];

    const int tid = threadIdx.x;
    const int sb = blockIdx.x * 64;
    const int h = blockIdx.y;
    const int r = tid >> 2;
    const int pg = tid & 3;

    {
        int s = sb + r;
        const float* qrow = qkv + (size_t)s * (3 * DIM) + h * HD;
        const float* krow = qrow + DIM;
#pragma unroll
        for (int u = 0; u < 4; u++) {
            int c = pg * 16 + u * 4;
            float4 qv = *(const float4*)(qrow + c);
            float4 kv = *(const float4*)(krow + c);
            float outq[4], outk[4];
#pragma unroll
            for (int pp = 0; pp < 2; pp++) {
                int ip = (c >> 1) + pp;
                float2 cspair = cstab[(s << 5) + ip];
                float cs = cspair.x, sn = cspair.y;
                float qx = pp ? qv.z : qv.x, qy = pp ? qv.w : qv.y;
                float kx = pp ? kv.z : kv.x, ky = pp ? kv.w : kv.y;
                outq[2 * pp + 0] = qx * cs - qy * sn;
                outq[2 * pp + 1] = qx * sn + qy * cs;
                outk[2 * pp + 0] = kx * cs - ky * sn;
                outk[2 * pp + 1] = kx * sn + ky * cs;
            }
            uint32_t qh0, ql0, qh1, ql1, kh0, kl0, kh1, kl1;
            split2(outq[0], outq[1], qh0, ql0);
            split2(outq[2], outq[3], qh1, ql1);
            split2(outk[0], outk[1], kh0, kl0);
            split2(outk[2], outk[3], kh1, kl1);
            __nv_bfloat16* qd = qc + (size_t)s * KC + h * 192 + c;
            __nv_bfloat16* kd = kc + (size_t)s * KC + h * 192 + c;
            *(uint32_t*)(qd)       = qh0; *(uint32_t*)(qd + 2)   = qh1;
            *(uint32_t*)(qd + 64)  = qh0; *(uint32_t*)(qd + 66)  = qh1;
            *(uint32_t*)(qd + 128) = ql0; *(uint32_t*)(qd + 130) = ql1;
            *(uint32_t*)(kd)       = kh0; *(uint32_t*)(kd + 2)   = kh1;
            *(uint32_t*)(kd + 64)  = kl0; *(uint32_t*)(kd + 66)  = kl1;
            *(uint32_t*)(kd + 128) = kh0; *(uint32_t*)(kd + 130) = kh1;
        }
    }

    {
        const float* vrow = qkv + (size_t)(sb + r) * (3 * DIM) + 2 * DIM + h * HD;
#pragma unroll
        for (int u = 0; u < 4; u++) {
            int c = pg * 16 + u * 4;
            *(float4*)&vsm[r][c] = *(const float4*)(vrow + c);
        }
    }
    __syncthreads();
    {
        int dcat = tid & 127;
        int sh = (tid >> 7) * 32;
        int d = dcat & 63;
        bool lo = dcat >= 64;
        uint32_t packs[16];
#pragma unroll
        for (int j = 0; j < 16; j++) {
            float f0 = vsm[sh + 2 * j][d];
            float f1 = vsm[sh + 2 * j + 1][d];
            uint32_t hi, lw;
            split2(f0, f1, hi, lw);
            packs[j] = lo ? lw : hi;
        }
        __nv_bfloat16* dst = vt + ((size_t)(h * 128 + dcat)) * S_LEN + sb + sh;
#pragma unroll
        for (int j = 0; j < 4; j++)
            *(uint4*)(dst + j * 8) = make_uint4(packs[4 * j], packs[4 * j + 1],
                                                packs[4 * j + 2], packs[4 * j + 3]);
    }
}

// ---------------------------------------------------------------------------
// Tensor-core sliding-window flash attention: BQ=64, 128 threads,
// single-buffered (3 CTAs/SM), interior tiles skip masking entirely.
// ---------------------------------------------------------------------------
#define QLD 200      // 192 + 8 pad
#define VLD 72       // 64 + 8 pad
#define SWA_SMEM (64 * QLD * 2 + 64 * QLD * 2 + 128 * VLD * 2)  // 69632

__global__ __launch_bounds__(128) void swa_mma_kernel(
    const __nv_bfloat16* __restrict__ qc, const __nv_bfloat16* __restrict__ kc,
    const __nv_bfloat16* __restrict__ vt, __nv_bfloat16* __restrict__ oc)
{
    extern __shared__ char smem[];
    __nv_bfloat16* Qs = (__nv_bfloat16*)smem;                      // [64][QLD]
    __nv_bfloat16* Ks = (__nv_bfloat16*)(smem + 64 * QLD * 2);     // [64][QLD]
    __nv_bfloat16* Vc = (__nv_bfloat16*)(smem + 2 * 64 * QLD * 2); // [128][VLD]

    const int tid = threadIdx.x;
    const int lane = tid & 31;
    const int w = tid >> 5;
    const int qbase = blockIdx.x * 64;
    const int h = blockIdx.y;
    const int lrow = lane & 15;
    const int lcol = (lane >> 4) * 8;

    {
#pragma unroll
        for (int i = 0; i < 12; i++) {
            int c = tid + i * 128;
            int row = c / 24, off = (c % 24) * 8;
            cp16(smem_u32(&Qs[row * QLD + off]),
                 qc + (size_t)(qbase + row) * KC + h * 192 + off);
        }
        asm volatile("cp.async.commit_group;");
    }

    float oacc[8][4];
#pragma unroll
    for (int b = 0; b < 8; b++)
#pragma unroll
        for (int q = 0; q < 4; q++) oacc[b][q] = 0.f;
    float mrun0 = -1e30f, mrun1 = -1e30f, lrun0 = 0.f, lrun1 = 0.f;

    const int qg0 = qbase + w * 16 + (lane >> 2);
    const int qg1 = qg0 + 8;

    for (int t = 0; t < 9; t++) {
        int kbase = qbase - 512 + t * 64;
        if (kbase < 0) continue;
        __syncthreads();

#pragma unroll
        for (int i = 0; i < 12; i++) {
            int c = tid + i * 128;
            int row = c / 24, off = (c % 24) * 8;
            cp16(smem_u32(&Ks[row * QLD + off]),
                 kc + (size_t)(kbase + row) * KC + h * 192 + off);
        }
#pragma unroll
        for (int i = 0; i < 8; i++) {
            int c = tid + i * 128;
            int dcat = c >> 3, j0 = (c & 7) * 8;
            cp16(smem_u32(&Vc[dcat * VLD + j0]),
                 vt + ((size_t)(h * 128 + dcat)) * S_LEN + kbase + j0);
        }
        asm volatile("cp.async.commit_group;");
        asm volatile("cp.async.wait_group 0;");
        __syncthreads();

        float sacc[8][4];
#pragma unroll
        for (int b = 0; b < 8; b++)
#pragma unroll
            for (int q = 0; q < 4; q++) sacc[b][q] = 0.f;
#pragma unroll
        for (int ks = 0; ks < 12; ks++) {
            uint32_t af[4];
            ldsm4(af, smem_u32(&Qs[(w * 16 + lrow) * QLD + ks * 16 + lcol]));
#pragma unroll
            for (int g = 0; g < 4; g++) {
                uint32_t bf[4];
                ldsm4(bf, smem_u32(&Ks[(g * 16 + lrow) * QLD + ks * 16 + lcol]));
                mma16816(sacc[g * 2 + 0], af, bf[0], bf[2]);
                mma16816(sacc[g * 2 + 1], af, bf[1], bf[3]);
            }
        }

        // Only diagonal / oldest tiles contain invalid pairs.
        const bool edge = (kbase == qbase) || (kbase == qbase - 512);
        if (edge) {
#pragma unroll
            for (int b = 0; b < 8; b++) {
                int j0 = kbase + b * 8 + (lane & 3) * 2;
#pragma unroll
                for (int q = 0; q < 4; q++) {
                    int kg = j0 + (q & 1);
                    int qg = (q < 2) ? qg0 : qg1;
                    bool valid = (kg <= qg) && (kg + (WIN - 1) >= qg);
                    sacc[b][q] = valid ? sacc[b][q] * 0.125f : -1e30f;
                }
            }
        } else {
#pragma unroll
            for (int b = 0; b < 8; b++)
#pragma unroll
                for (int q = 0; q < 4; q++) sacc[b][q] *= 0.125f;
        }

        float rm0 = -1e30f, rm1 = -1e30f;
#pragma unroll
        for (int b = 0; b < 8; b++) {
            rm0 = fmaxf(rm0, fmaxf(sacc[b][0], sacc[b][1]));
            rm1 = fmaxf(rm1, fmaxf(sacc[b][2], sacc[b][3]));
        }
        rm0 = fmaxf(rm0, __shfl_xor_sync(0xffffffffu, rm0, 1));
        rm0 = fmaxf(rm0, __shfl_xor_sync(0xffffffffu, rm0, 2));
        rm1 = fmaxf(rm1, __shfl_xor_sync(0xffffffffu, rm1, 1));
        rm1 = fmaxf(rm1, __shfl_xor_sync(0xffffffffu, rm1, 2));

        float mn0 = fmaxf(mrun0, rm0), mn1 = fmaxf(mrun1, rm1);
        float sc0 = __expf(mrun0 - mn0), sc1 = __expf(mrun1 - mn1);
        float rs0 = 0.f, rs1 = 0.f;
        if (edge) {
#pragma unroll
            for (int b = 0; b < 8; b++) {
                float p0 = (sacc[b][0] > -5e29f) ? __expf(sacc[b][0] - mn0) : 0.f;
                float p1 = (sacc[b][1] > -5e29f) ? __expf(sacc[b][1] - mn0) : 0.f;
                float p2 = (sacc[b][2] > -5e29f) ? __expf(sacc[b][2] - mn1) : 0.f;
                float p3 = (sacc[b][3] > -5e29f) ? __expf(sacc[b][3] - mn1) : 0.f;
                sacc[b][0] = p0; sacc[b][1] = p1; sacc[b][2] = p2; sacc[b][3] = p3;
                rs0 += p0 + p1;
                rs1 += p2 + p3;
            }
        } else {
#pragma unroll
            for (int b = 0; b < 8; b++) {
                float p0 = __expf(sacc[b][0] - mn0);
                float p1 = __expf(sacc[b][1] - mn0);
                float p2 = __expf(sacc[b][2] - mn1);
                float p3 = __expf(sacc[b][3] - mn1);
                sacc[b][0] = p0; sacc[b][1] = p1; sacc[b][2] = p2; sacc[b][3] = p3;
                rs0 += p0 + p1;
                rs1 += p2 + p3;
            }
        }
        rs0 += __shfl_xor_sync(0xffffffffu, rs0, 1);
        rs0 += __shfl_xor_sync(0xffffffffu, rs0, 2);
        rs1 += __shfl_xor_sync(0xffffffffu, rs1, 1);
        rs1 += __shfl_xor_sync(0xffffffffu, rs1, 2);
        lrun0 = lrun0 * sc0 + rs0;
        lrun1 = lrun1 * sc1 + rs1;
        mrun0 = mn0;
        mrun1 = mn1;
#pragma unroll
        for (int b = 0; b < 8; b++) {
            oacc[b][0] *= sc0; oacc[b][1] *= sc0;
            oacc[b][2] *= sc1; oacc[b][3] *= sc1;
        }

#pragma unroll
        for (int ks = 0; ks < 4; ks++) {
            uint32_t aH[4], aL[4];
            split2(sacc[2 * ks][0],     sacc[2 * ks][1],     aH[0], aL[0]);
            split2(sacc[2 * ks][2],     sacc[2 * ks][3],     aH[1], aL[1]);
            split2(sacc[2 * ks + 1][0], sacc[2 * ks + 1][1], aH[2], aL[2]);
            split2(sacc[2 * ks + 1][2], sacc[2 * ks + 1][3], aH[3], aL[3]);
#pragma unroll
            for (int db = 0; db < 4; db++) {
                uint32_t bh[4], bl[4];
                ldsm4(bh, smem_u32(&Vc[(db * 16 + lrow) * VLD + ks * 16 + lcol]));
                ldsm4(bl, smem_u32(&Vc[((64 + db * 16) + lrow) * VLD + ks * 16 + lcol]));
                mma16816(oacc[2 * db + 0], aH, bh[0], bh[2]);
                mma16816(oacc[2 * db + 1], aH, bh[1], bh[3]);
                mma16816(oacc[2 * db + 0], aL, bh[0], bh[2]);
                mma16816(oacc[2 * db + 1], aL, bh[1], bh[3]);
                mma16816(oacc[2 * db + 0], aH, bl[0], bl[2]);
                mma16816(oacc[2 * db + 1], aH, bl[1], bl[3]);
            }
        }
    }

    float inv0 = 1.0f / lrun0, inv1 = 1.0f / lrun1;
#pragma unroll
    for (int b = 0; b < 8; b++) {
        int d = b * 8 + (lane & 3) * 2;
        uint32_t hi0, lo0, hi1, lo1;
        split2(oacc[b][0] * inv0, oacc[b][1] * inv0, hi0, lo0);
        split2(oacc[b][2] * inv1, oacc[b][3] * inv1, hi1, lo1);
        __nv_bfloat16* d0 = oc + (size_t)qg0 * KC + h * HD + d;
        __nv_bfloat16* d1 = oc + (size_t)qg1 * KC + h * HD + d;
        *(uint32_t*)(d0)        = hi0;
        *(uint32_t*)(d0 + 1024) = hi0;
        *(uint32_t*)(d0 + 2048) = lo0;
        *(uint32_t*)(d1)        = hi1;
        *(uint32_t*)(d1 + 1024) = hi1;
        *(uint32_t*)(d1 + 2048) = lo1;
    }
}

// ---------------------------------------------------------------------------
// Launch
// ---------------------------------------------------------------------------
extern "C" void kernel_launch(void* const* d_in, const int* in_sizes, int n_in,
                              void* d_out, int out_size)
{
    (void)in_sizes; (void)n_in; (void)out_size;

    const float* x = (const float*)d_in[0];
    const float* W[4] = {(const float*)d_in[1], (const float*)d_in[2],
                         (const float*)d_in[3], (const float*)d_in[4]};
    float* out = (float*)d_out;

    float* qkv;
    float2* cstab;
    __nv_bfloat16 *xc, *oc, *wc, *qc, *kc, *vt;
    cudaGetSymbolAddress((void**)&qkv, g_qkv);
    cudaGetSymbolAddress((void**)&cstab, g_cs);
    cudaGetSymbolAddress((void**)&xc, g_xc);
    cudaGetSymbolAddress((void**)&oc, g_oc);
    cudaGetSymbolAddress((void**)&wc, g_wc);
    cudaGetSymbolAddress((void**)&qc, g_qc);
    cudaGetSymbolAddress((void**)&kc, g_kc);
    cudaGetSymbolAddress((void**)&vt, g_vt);

    cudaFuncSetAttribute(gemm_mma<128>, cudaFuncAttributeMaxDynamicSharedMemorySize, GEMM_SMEM_128);
    cudaFuncSetAttribute(gemm_mma<64>,  cudaFuncAttributeMaxDynamicSharedMemorySize, GEMM_SMEM_64);
    cudaFuncSetAttribute(swa_mma_kernel, cudaFuncAttributeMaxDynamicSharedMemorySize, SWA_SMEM);

    const int nx = S_LEN * DIM;
    const int nw = DIM * DIM;

    sincos_kernel<<<(S_LEN * 32) / 256, 256>>>(cstab);
    split3_kernel<<<nx / 4 / 256, 256>>>(x, xc, nx);
    split3_w_kernel<<<dim3(nw / 4 / 256, 4), 256>>>(W[0], W[1], W[2], W[3], wc);

    gemm_mma<128><<<dim3(S_LEN / BM, 3 * DIM / 128), 128, GEMM_SMEM_128>>>(
        xc, wc, qkv, 3 * DIM);

    rope_split_kernel<<<dim3(S_LEN / 64, NH), 256>>>(qkv, cstab, qc, kc, vt);

    swa_mma_kernel<<<dim3(S_LEN / 64, NH), 128, SWA_SMEM>>>(qc, kc, vt, oc);

    gemm_mma<64><<<dim3(S_LEN / BM, DIM / 64), 128, GEMM_SMEM_64>>>(
        oc, wc + (size_t)3 * DIM * KC, out, DIM);
}